// round 15
// baseline (speedup 1.0000x reference)
#include <cuda_runtime.h>
#include <cuda_bf16.h>
#include <math.h>
#include <stdint.h>

// ---------------- problem constants ----------------
constexpr int cB   = 32;
constexpr int cSQ  = 200;
constexpr int cSKV = 200;
constexpr int cD   = 1024;
constexpr int cH   = 16;
constexpr int cHD  = 64;
constexpr int cL   = 6;
constexpr int cFF  = 2048;
constexpr int cM   = cB * cSQ;   // 6400

// ---------------- scratch ----------------
__device__ float g_x[cM * cD];
__device__ float g_q[cM * cD];
__device__ float g_k[cM * cD];
__device__ float g_v[cM * cD];
__device__ float g_a[cM * cD];
__device__ float g_f[cM * cFF];
__device__ float g_kc[cL][cM * cD];   // precomputed cross-attn K per layer
__device__ float g_vc[cL][cM * cD];   // precomputed cross-attn V per layer

constexpr size_t WBLK  = (size_t)cL * cD * cD;
constexpr size_t W1OFF = 8 * WBLK;
constexpr size_t W1SZ  = (size_t)cL * cD * cFF;
constexpr size_t W2OFF = W1OFF + W1SZ;
constexpr size_t WTOT  = W2OFF + W1SZ;

__device__ __align__(16) __nv_bfloat16 g_whi[WTOT];
__device__ __align__(16) __nv_bfloat16 g_wlo[WTOT];
__device__ __align__(16) __nv_bfloat16 g_ahi[cM * cFF];
__device__ __align__(16) __nv_bfloat16 g_alo[cM * cFF];
__device__ __align__(16) __nv_bfloat16 g_keyhi[cM * cD];
__device__ __align__(16) __nv_bfloat16 g_keylo[cM * cD];
__device__ __align__(16) __nv_bfloat16 g_valhi[cM * cD];
__device__ __align__(16) __nv_bfloat16 g_vallo[cM * cD];

// ---------------- fp32 -> bf16 hi/lo split ----------------
__global__ void split4_kernel(const float* __restrict__ in,
                              __nv_bfloat16* __restrict__ hi,
                              __nv_bfloat16* __restrict__ lo, int n4)
{
    int i = blockIdx.x * blockDim.x + threadIdx.x;
    if (i >= n4) return;
    float4 v = reinterpret_cast<const float4*>(in)[i];
    __nv_bfloat16 h0 = __float2bfloat16(v.x);
    __nv_bfloat16 h1 = __float2bfloat16(v.y);
    __nv_bfloat16 h2 = __float2bfloat16(v.z);
    __nv_bfloat16 h3 = __float2bfloat16(v.w);
    __nv_bfloat16 l0 = __float2bfloat16(v.x - __bfloat162float(h0));
    __nv_bfloat16 l1 = __float2bfloat16(v.y - __bfloat162float(h1));
    __nv_bfloat16 l2 = __float2bfloat16(v.z - __bfloat162float(h2));
    __nv_bfloat16 l3 = __float2bfloat16(v.w - __bfloat162float(h3));
    __nv_bfloat162* H = reinterpret_cast<__nv_bfloat162*>(hi);
    __nv_bfloat162* L = reinterpret_cast<__nv_bfloat162*>(lo);
    H[2 * i]     = __nv_bfloat162(h0, h1);
    H[2 * i + 1] = __nv_bfloat162(h2, h3);
    L[2 * i]     = __nv_bfloat162(l0, l1);
    L[2 * i + 1] = __nv_bfloat162(l2, l3);
}

// ---------------- embedding + positional encoding ----------------
__global__ void embed_kernel(const int* __restrict__ tok,
                             const float* __restrict__ emb,
                             float* __restrict__ x)
{
    int idx = blockIdx.x * blockDim.x + threadIdx.x;
    if (idx >= cM * (cD / 2)) return;
    int p = idx & (cD / 2 - 1);
    int t = idx >> 9;
    int s = t % cSQ;
    int id = tok[t];
    int j = p * 2;
    float div = __powf(10000.0f, (float)j / (float)cD);
    float ang = (float)s / div;
    float sv, cv;
    sincosf(ang, &sv, &cv);
    const float* er = emb + (size_t)id * cD + j;
    float2 out;
    out.x = er[0] + sv;
    out.y = er[1] + cv;
    *reinterpret_cast<float2*>(x + (size_t)t * cD + j) = out;
}

// ---------------- layernorm (optionally writing vectorized bf16 hi/lo split) ----------------
template<bool SPLIT>
__global__ void ln_kernel(const float* __restrict__ x,
                          const float* __restrict__ g,
                          const float* __restrict__ b,
                          float* __restrict__ y,
                          __nv_bfloat16* __restrict__ hi,
                          __nv_bfloat16* __restrict__ lo)
{
    __shared__ float red[64];
    int row = blockIdx.x;
    const float* xr = x + (size_t)row * cD;
    float s = 0.f, s2 = 0.f;
    for (int i = threadIdx.x; i < cD; i += blockDim.x) {
        float v = xr[i];
        s += v;
        s2 = fmaf(v, v, s2);
    }
    #pragma unroll
    for (int o = 16; o; o >>= 1) {
        s  += __shfl_xor_sync(0xffffffffu, s,  o);
        s2 += __shfl_xor_sync(0xffffffffu, s2, o);
    }
    int w = threadIdx.x >> 5;
    if ((threadIdx.x & 31) == 0) { red[w] = s; red[32 + w] = s2; }
    __syncthreads();
    if (threadIdx.x < 32) {
        int nw = blockDim.x >> 5;
        s  = (threadIdx.x < nw) ? red[threadIdx.x]      : 0.f;
        s2 = (threadIdx.x < nw) ? red[32 + threadIdx.x] : 0.f;
        #pragma unroll
        for (int o = 16; o; o >>= 1) {
            s  += __shfl_xor_sync(0xffffffffu, s,  o);
            s2 += __shfl_xor_sync(0xffffffffu, s2, o);
        }
        if (threadIdx.x == 0) { red[0] = s; red[32] = s2; }
    }
    __syncthreads();
    float mean = red[0] * (1.0f / cD);
    float var  = red[32] * (1.0f / cD) - mean * mean;
    float inv  = rsqrtf(var + 1e-9f);
    if (SPLIT) {
        for (int i = threadIdx.x * 2; i < cD; i += blockDim.x * 2) {
            float v0 = (xr[i]     - mean) * inv * g[i]     + b[i];
            float v1 = (xr[i + 1] - mean) * inv * g[i + 1] + b[i + 1];
            __nv_bfloat16 h0 = __float2bfloat16(v0);
            __nv_bfloat16 h1 = __float2bfloat16(v1);
            __nv_bfloat16 l0 = __float2bfloat16(v0 - __bfloat162float(h0));
            __nv_bfloat16 l1 = __float2bfloat16(v1 - __bfloat162float(h1));
            *reinterpret_cast<__nv_bfloat162*>(&hi[(size_t)row * cD + i]) = __nv_bfloat162(h0, h1);
            *reinterpret_cast<__nv_bfloat162*>(&lo[(size_t)row * cD + i]) = __nv_bfloat162(l0, l1);
        }
    } else {
        float* yr = y + (size_t)row * cD;
        for (int i = threadIdx.x; i < cD; i += blockDim.x)
            yr[i] = (xr[i] - mean) * inv * g[i] + b[i];
    }
}

// ---------------- GEMM primitives ----------------
#define TBM 128
#define TBN 128
#define TBK 32

constexpr int A_ROWB = 80;
constexpr int AS_SPL = TBM * A_ROWB;         // 10240
constexpr int A_BUFB = 2 * AS_SPL;
constexpr int B_ROWB = 272;
constexpr int BS_SPL = TBK * B_ROWB;         // 8704
constexpr int B_BUFB = 2 * BS_SPL;
constexpr int STAGEB = A_BUFB + B_BUFB;      // 37888
constexpr int GEMM_SMEM = 2 * STAGEB;        // 75776

__device__ __forceinline__ void cp16(uint32_t dst, const void* src)
{
    asm volatile("cp.async.cg.shared.global [%0], [%1], 16;\n" :: "r"(dst), "l"(src));
}
__device__ __forceinline__ void cp_commit()
{
    asm volatile("cp.async.commit_group;\n");
}
template<int N> __device__ __forceinline__ void cp_wait()
{
    asm volatile("cp.async.wait_group %0;\n" :: "n"(N));
}
__device__ __forceinline__ void ldm_x4(uint32_t* r, uint32_t addr)
{
    asm volatile("ldmatrix.sync.aligned.m8n8.x4.shared.b16 {%0,%1,%2,%3}, [%4];\n"
                 : "=r"(r[0]), "=r"(r[1]), "=r"(r[2]), "=r"(r[3]) : "r"(addr));
}
__device__ __forceinline__ void ldm_x4t(uint32_t* r, uint32_t addr)
{
    asm volatile("ldmatrix.sync.aligned.m8n8.x4.trans.shared.b16 {%0,%1,%2,%3}, [%4];\n"
                 : "=r"(r[0]), "=r"(r[1]), "=r"(r[2]), "=r"(r[3]) : "r"(addr));
}
__device__ __forceinline__ void mma_bf16(float* c, const uint32_t* a, const uint32_t* b)
{
    asm volatile("mma.sync.aligned.m16n8k16.row.col.f32.bf16.bf16.f32 "
                 "{%0,%1,%2,%3}, {%4,%5,%6,%7}, {%8,%9}, {%0,%1,%2,%3};\n"
                 : "+f"(c[0]), "+f"(c[1]), "+f"(c[2]), "+f"(c[3])
                 : "r"(a[0]), "r"(a[1]), "r"(a[2]), "r"(a[3]), "r"(b[0]), "r"(b[1]));
}

template<bool HAS_BIAS, bool HAS_RES, bool DO_RELU>
__device__ __forceinline__ void gemm_body(
    int M, int N, int K,
    const __nv_bfloat16* __restrict__ Ahi,
    const __nv_bfloat16* __restrict__ Alo,
    const __nv_bfloat16* __restrict__ Bhi,
    const __nv_bfloat16* __restrict__ Blo,
    const float* __restrict__ bias,
    const float* __restrict__ R,
    float* __restrict__ C,
    char* smem)
{
    const uint32_t sb = (uint32_t)__cvta_generic_to_shared(smem);

    const int tid  = threadIdx.x;
    const int blockM = blockIdx.y * TBM;
    const int blockN = blockIdx.x * TBN;

    const int am = tid >> 1;
    const int ac = (tid & 1) * 2;
    const int bk = tid >> 3;
    const int bc = (tid & 7) * 2;

    const __nv_bfloat16* Ah = Ahi + (size_t)(blockM + am) * K;
    const __nv_bfloat16* Al = Alo + (size_t)(blockM + am) * K;

    auto load_stage = [&](int kt, int buf) {
        const uint32_t abase = sb + buf * STAGEB;
        const uint32_t bbase = sb + buf * STAGEB + A_BUFB;
        int kofs = kt * TBK;
        #pragma unroll
        for (int c = 0; c < 2; c++) {
            uint32_t d = abase + am * A_ROWB + (ac + c) * 16;
            cp16(d,           Ah + kofs + (ac + c) * 8);
            cp16(d + AS_SPL,  Al + kofs + (ac + c) * 8);
        }
        const __nv_bfloat16* Bh = Bhi + (size_t)(kofs + bk) * N + blockN;
        const __nv_bfloat16* Bl = Blo + (size_t)(kofs + bk) * N + blockN;
        #pragma unroll
        for (int c = 0; c < 2; c++) {
            uint32_t d = bbase + bk * B_ROWB + (bc + c) * 16;
            cp16(d,           Bh + (bc + c) * 8);
            cp16(d + BS_SPL,  Bl + (bc + c) * 8);
        }
    };

    const int warp = tid >> 5;
    const int lane = tid & 31;
    const int warp_m = (warp >> 2) * 64;
    const int warp_n = (warp & 3) * 32;

    const int a_row = lane & 15;
    const int a_kc  = lane >> 4;
    const int b_row = (lane & 7) + ((lane >> 3) & 1) * 8;
    const int b_nc  = (lane >> 4) * 8;

    float acc[4][4][4] = {};

    const int tiles = K / TBK;
    load_stage(0, 0);
    cp_commit();

    for (int kt = 0; kt < tiles; kt++) {
        if (kt + 1 < tiles) load_stage(kt + 1, (kt + 1) & 1);
        cp_commit();
        cp_wait<1>();
        __syncthreads();

        const int buf = kt & 1;
        const uint32_t abase = sb + buf * STAGEB;
        const uint32_t bbase = sb + buf * STAGEB + A_BUFB;

        #pragma unroll
        for (int ks = 0; ks < 2; ks++) {
            const int k0 = ks * 16;
            uint32_t ah[4][4], al[4][4];
            #pragma unroll
            for (int mt = 0; mt < 4; mt++) {
                uint32_t ar = abase + (warp_m + mt * 16 + a_row) * A_ROWB
                            + ((k0 >> 3) + a_kc) * 16;
                ldm_x4(ah[mt], ar);
                ldm_x4(al[mt], ar + AS_SPL);
            }
            uint32_t bh[4][2], bl[4][2];
            #pragma unroll
            for (int g = 0; g < 2; g++) {
                uint32_t br = bbase + (k0 + b_row) * B_ROWB
                            + (warp_n + g * 16 + b_nc) * 2;
                uint32_t r[4];
                ldm_x4t(r, br);
                bh[2 * g][0] = r[0]; bh[2 * g][1] = r[1];
                bh[2 * g + 1][0] = r[2]; bh[2 * g + 1][1] = r[3];
                ldm_x4t(r, br + BS_SPL);
                bl[2 * g][0] = r[0]; bl[2 * g][1] = r[1];
                bl[2 * g + 1][0] = r[2]; bl[2 * g + 1][1] = r[3];
            }
            #pragma unroll
            for (int mt = 0; mt < 4; mt++)
                #pragma unroll
                for (int nt = 0; nt < 4; nt++) {
                    mma_bf16(acc[mt][nt], ah[mt], bh[nt]);
                    mma_bf16(acc[mt][nt], ah[mt], bl[nt]);
                    mma_bf16(acc[mt][nt], al[mt], bh[nt]);
                }
        }
        __syncthreads();
    }

    #pragma unroll
    for (int mt = 0; mt < 4; mt++) {
        #pragma unroll
        for (int nt = 0; nt < 4; nt++) {
            int row0 = blockM + warp_m + mt * 16 + (lane >> 2);
            int col  = blockN + warp_n + nt * 8 + (lane & 3) * 2;
            #pragma unroll
            for (int h = 0; h < 2; h++) {
                int row = row0 + h * 8;
                float2 v;
                v.x = acc[mt][nt][2 * h];
                v.y = acc[mt][nt][2 * h + 1];
                if (HAS_BIAS) {
                    float2 bz = *reinterpret_cast<const float2*>(&bias[col]);
                    v.x += bz.x; v.y += bz.y;
                }
                if (HAS_RES) {
                    float2 rz = *reinterpret_cast<const float2*>(&R[(size_t)row * N + col]);
                    v.x += rz.x; v.y += rz.y;
                }
                if (DO_RELU) { v.x = fmaxf(v.x, 0.f); v.y = fmaxf(v.y, 0.f); }
                *reinterpret_cast<float2*>(&C[(size_t)row * N + col]) = v;
            }
        }
    }
}

template<bool HAS_BIAS, bool HAS_RES, bool DO_RELU>
__global__ __launch_bounds__(256, 2)
void bgemm_kernel(int M, int N, int K,
                  const __nv_bfloat16* __restrict__ Ahi,
                  const __nv_bfloat16* __restrict__ Alo,
                  const __nv_bfloat16* __restrict__ Bhi,
                  const __nv_bfloat16* __restrict__ Blo,
                  const float* __restrict__ bias,
                  const float* __restrict__ R,
                  float* __restrict__ C)
{
    extern __shared__ char smem[];
    gemm_body<HAS_BIAS, HAS_RES, DO_RELU>(M, N, K, Ahi, Alo, Bhi, Blo, bias, R, C, smem);
}

// ---- z-batched GEMM ----
struct GJob {
    const __nv_bfloat16 *Ahi, *Alo, *Bhi, *Blo;
    const float* bias;
    float* C;
};
struct GJobs { GJob j[12]; };

__global__ __launch_bounds__(256, 2)
void bgemm_batch_kernel(int M, int N, int K, GJobs jobs)
{
    extern __shared__ char smem[];
    const GJob jb = jobs.j[blockIdx.z];
    gemm_body<true, false, false>(M, N, K, jb.Ahi, jb.Alo, jb.Bhi, jb.Blo,
                                  jb.bias, nullptr, jb.C, smem);
}

// ---------------- fused attention: 2 threads per query row ----------------
constexpr int ATTN_SMEM = 2 * cSKV * cHD * (int)sizeof(float);  // 102400 B
constexpr int HHD = cHD / 2;   // 32 dims per pair-thread

__global__ __launch_bounds__(512, 1)
void attn_kernel(const float* __restrict__ Q,
                 const float* __restrict__ Km,
                 const float* __restrict__ Vm,
                 float* __restrict__ O,
                 const int* __restrict__ tok,
                 int causal)
{
    extern __shared__ float sm[];
    float* Ks = sm;
    float* Vs = sm + cSKV * cHD;
    __shared__ int padk[cSKV];

    int bh = blockIdx.x;
    int b  = bh / cH, h = bh % cH;
    const float* Kbase = Km + (size_t)b * cSKV * cD + h * cHD;
    const float* Vbase = Vm + (size_t)b * cSKV * cD + h * cHD;

    for (int idx = threadIdx.x; idx < cSKV * cHD; idx += blockDim.x) {
        int kk = idx >> 6, d = idx & 63;
        Ks[idx] = Kbase[(size_t)kk * cD + d];
        Vs[idx] = Vbase[(size_t)kk * cD + d];
    }
    if (causal)
        for (int idx = threadIdx.x; idx < cSKV; idx += blockDim.x)
            padk[idx] = (tok[b * cSQ + idx] == 0);
    __syncthreads();

    const int t    = threadIdx.x;
    const int qi   = t >> 1;
    const int half = t & 1;
    const bool valid = (qi < cSQ);
    const int qq = valid ? qi : (cSQ - 1);       // keep lanes converged

    const int lane = t & 31;
    const uint32_t pairMask = 0x3u << (lane & 30);

    float rq[HHD];
    const float* Qr = Q + (size_t)(b * cSQ + qq) * cD + h * cHD + half * HHD;
    #pragma unroll
    for (int d = 0; d < HHD; d++) rq[d] = Qr[d] * 0.125f;

    float m = -INFINITY, l = 0.f;
    float acc[HHD];
    #pragma unroll
    for (int d = 0; d < HHD; d++) acc[d] = 0.f;

    int kmax = causal ? (qq + 1) : cSKV;
    for (int k = 0; k < kmax; k++) {
        if (causal && padk[k]) continue;
        const float* kr = &Ks[k * cHD + half * HHD];
        float s0 = 0.f, s1 = 0.f, s2 = 0.f, s3 = 0.f;
        #pragma unroll
        for (int d = 0; d < HHD; d += 4) {
            s0 = fmaf(rq[d + 0], kr[d + 0], s0);
            s1 = fmaf(rq[d + 1], kr[d + 1], s1);
            s2 = fmaf(rq[d + 2], kr[d + 2], s2);
            s3 = fmaf(rq[d + 3], kr[d + 3], s3);
        }
        float part = (s0 + s1) + (s2 + s3);
        float s = part + __shfl_xor_sync(pairMask, part, 1);
        float mn = fmaxf(m, s);
        float f  = __expf(m - mn);
        float e  = __expf(s - mn);
        l = l * f + e;
        const float* vr = &Vs[k * cHD + half * HHD];
        #pragma unroll
        for (int d = 0; d < HHD; d++)
            acc[d] = fmaf(acc[d], f, e * vr[d]);
        m = mn;
    }
    if (valid) {
        float inv = 1.0f / l;
        float* Or = O + (size_t)(b * cSQ + qq) * cD + h * cHD + half * HHD;
        #pragma unroll
        for (int d = 0; d < HHD; d++) Or[d] = acc[d] * inv;
    }
}

// ---------------- host-side helpers ----------------
typedef const __nv_bfloat16* bfp;

static inline void split_arr(const float* in, __nv_bfloat16* hi, __nv_bfloat16* lo, size_t n)
{
    int n4 = (int)(n / 4);
    split4_kernel<<<(n4 + 255) / 256, 256>>>(in, hi, lo, n4);
}

template<bool HB, bool HR, bool RL>
static inline void bgemm(bfp Ahi, bfp Alo, bfp Bhi, bfp Blo,
                         const float* bias, const float* R, float* C,
                         int M, int N, int K)
{
    dim3 grid(N / TBN, M / TBM);
    bgemm_kernel<HB, HR, RL><<<grid, 256, GEMM_SMEM>>>(M, N, K, Ahi, Alo, Bhi, Blo, bias, R, C);
}

extern "C" void kernel_launch(void* const* d_in, const int* in_sizes, int n_in,
                              void* d_out, int out_size)
{
    const int*   query = (const int*)d_in[0];
    const float* key   = (const float*)d_in[1];
    const float* value = (const float*)d_in[2];
    const float* emb   = (const float*)d_in[3];

    const float* P[32];
    for (int i = 0; i < n_in && i < 32; i++) P[i] = (const float*)d_in[i];

    const float *ln1_g, *ln1_b, *ln2_g, *ln2_b, *ln3_g, *ln3_b;
    const float *Wq_s, *Wk_s, *Wv_s, *Wo_s, *Wq_c, *Wk_c, *Wv_c, *Wo_c;
    const float *bq_s, *bk_s, *bv_s, *bq_c, *bk_c, *bv_c;
    const float *W1, *bf1, *W2, *bf2, *lnf_g, *lnf_b;

    bool dict_order = (n_in > 11) && (in_sizes[11] > 1000000);
    if (dict_order) {
        ln1_g = P[4];  ln2_g = P[5];  ln3_g = P[6];
        ln1_b = P[7];  ln2_b = P[8];  ln3_b = P[9];
        Wq_s = P[10]; Wk_s = P[11]; Wv_s = P[12]; Wo_s = P[13];
        Wq_c = P[14]; Wk_c = P[15]; Wv_c = P[16]; Wo_c = P[17];
        bq_s = P[18]; bk_s = P[19]; bv_s = P[20];
        bq_c = P[21]; bk_c = P[22]; bv_c = P[23];
        W1 = P[24]; bf1 = P[25]; W2 = P[26]; bf2 = P[27];
        lnf_g = P[28]; lnf_b = P[29];
    } else {
        ln1_g = P[4];  ln1_b = P[5];  ln2_g = P[6];
        ln2_b = P[7];  ln3_g = P[8];  ln3_b = P[9];
        Wq_s = P[10]; bq_s = P[11]; Wk_s = P[12]; bk_s = P[13];
        Wv_s = P[14]; bv_s = P[15]; Wo_s = P[16];
        Wq_c = P[17]; bq_c = P[18]; Wk_c = P[19]; bk_c = P[20];
        Wv_c = P[21]; bv_c = P[22]; Wo_c = P[23];
        W1 = P[24]; bf1 = P[25]; W2 = P[26]; bf2 = P[27];
        lnf_g = P[28]; lnf_b = P[29];
    }

    float *x, *q, *k, *v, *a, *f, *kc, *vc;
    cudaGetSymbolAddress((void**)&x, g_x);
    cudaGetSymbolAddress((void**)&q, g_q);
    cudaGetSymbolAddress((void**)&k, g_k);
    cudaGetSymbolAddress((void**)&v, g_v);
    cudaGetSymbolAddress((void**)&a, g_a);
    cudaGetSymbolAddress((void**)&f, g_f);
    cudaGetSymbolAddress((void**)&kc, g_kc);
    cudaGetSymbolAddress((void**)&vc, g_vc);

    __nv_bfloat16 *whi, *wlo, *ahi, *alo, *khi, *klo, *vhi, *vlo;
    cudaGetSymbolAddress((void**)&whi, g_whi);
    cudaGetSymbolAddress((void**)&wlo, g_wlo);
    cudaGetSymbolAddress((void**)&ahi, g_ahi);
    cudaGetSymbolAddress((void**)&alo, g_alo);
    cudaGetSymbolAddress((void**)&khi, g_keyhi);
    cudaGetSymbolAddress((void**)&klo, g_keylo);
    cudaGetSymbolAddress((void**)&vhi, g_valhi);
    cudaGetSymbolAddress((void**)&vlo, g_vallo);

    cudaFuncSetAttribute(attn_kernel,
                         cudaFuncAttributeMaxDynamicSharedMemorySize, ATTN_SMEM);
    cudaFuncSetAttribute(bgemm_kernel<true, false, false>,
                         cudaFuncAttributeMaxDynamicSharedMemorySize, GEMM_SMEM);
    cudaFuncSetAttribute(bgemm_kernel<true, false, true>,
                         cudaFuncAttributeMaxDynamicSharedMemorySize, GEMM_SMEM);
    cudaFuncSetAttribute(bgemm_kernel<false, true, false>,
                         cudaFuncAttributeMaxDynamicSharedMemorySize, GEMM_SMEM);
    cudaFuncSetAttribute(bgemm_kernel<true, true, false>,
                         cudaFuncAttributeMaxDynamicSharedMemorySize, GEMM_SMEM);
    cudaFuncSetAttribute(bgemm_batch_kernel,
                         cudaFuncAttributeMaxDynamicSharedMemorySize, GEMM_SMEM);

    const size_t WD  = (size_t)cD * cD;
    const size_t WF1 = (size_t)cD * cFF;
    const size_t KVSTRIDE = (size_t)cM * cD;

    // ---- launches 1-5: splits needed by the cross-KV batch ----
    split_arr(key,   khi, klo, KVSTRIDE);                          // 1
    split_arr(value, vhi, vlo, KVSTRIDE);                          // 2
    split_arr(Wk_c, whi + 5 * WBLK, wlo + 5 * WBLK, WBLK);         // 3
    split_arr(Wv_c, whi + 6 * WBLK, wlo + 6 * WBLK, WBLK);         // 4
    split_arr(Wq_s, whi + 0 * WBLK, wlo + 0 * WBLK, WBLK);         // 5

    // ---- launch 6 (profiled): all 12 cross-attn K/V GEMMs in one batch ----
    {
        GJobs jobs;
        for (int l = 0; l < cL; l++) {
            jobs.j[2 * l]     = { khi, klo, whi + 5 * WBLK + l * WD, wlo + 5 * WBLK + l * WD,
                                  bk_c + l * cD, kc + l * KVSTRIDE };
            jobs.j[2 * l + 1] = { vhi, vlo, whi + 6 * WBLK + l * WD, wlo + 6 * WBLK + l * WD,
                                  bv_c + l * cD, vc + l * KVSTRIDE };
        }
        dim3 grid(cD / TBN, cM / TBM, 12);
        bgemm_batch_kernel<<<grid, 256, GEMM_SMEM>>>(cM, cD, cD, jobs);
    }

    // ---- remaining weight splits ----
    split_arr(Wk_s, whi + 1 * WBLK, wlo + 1 * WBLK, WBLK);
    split_arr(Wv_s, whi + 2 * WBLK, wlo + 2 * WBLK, WBLK);
    split_arr(Wo_s, whi + 3 * WBLK, wlo + 3 * WBLK, WBLK);
    split_arr(Wq_c, whi + 4 * WBLK, wlo + 4 * WBLK, WBLK);
    split_arr(Wo_c, whi + 7 * WBLK, wlo + 7 * WBLK, WBLK);
    split_arr(W1, whi + W1OFF, wlo + W1OFF, W1SZ);
    split_arr(W2, whi + W2OFF, wlo + W2OFF, W1SZ);

    // x = emb[query] + PE
    embed_kernel<<<(cM * (cD / 2) + 255) / 256, 256>>>(query, emb, x);

    for (int l = 0; l < cL; l++) {
        // --- self attention: LN(split) -> batched QKV -> attn -> Wo(+res) ---
        ln_kernel<true><<<cM, 256>>>(x, ln1_g + l * cD, ln1_b + l * cD, nullptr, ahi, alo);
        {
            GJobs jobs;
            jobs.j[0] = { ahi, alo, whi + 0 * WBLK + l * WD, wlo + 0 * WBLK + l * WD,
                          bq_s + l * cD, q };
            jobs.j[1] = { ahi, alo, whi + 1 * WBLK + l * WD, wlo + 1 * WBLK + l * WD,
                          bk_s + l * cD, k };
            jobs.j[2] = { ahi, alo, whi + 2 * WBLK + l * WD, wlo + 2 * WBLK + l * WD,
                          bv_s + l * cD, v };
            dim3 grid(cD / TBN, cM / TBM, 3);
            bgemm_batch_kernel<<<grid, 256, GEMM_SMEM>>>(cM, cD, cD, jobs);
        }
        attn_kernel<<<cB * cH, 512, ATTN_SMEM>>>(q, k, v, a, query, 1);
        split_arr(a, ahi, alo, KVSTRIDE);
        bgemm<false, true, false>(ahi, alo, whi + 3 * WBLK + l * WD, wlo + 3 * WBLK + l * WD,
                                  nullptr, x, x, cM, cD, cD);

        // --- cross attention (K,V precomputed) ---
        ln_kernel<true><<<cM, 256>>>(x, ln2_g + l * cD, ln2_b + l * cD, nullptr, ahi, alo);
        bgemm<true, false, false>(ahi, alo, whi + 4 * WBLK + l * WD, wlo + 4 * WBLK + l * WD,
                                  bq_c + l * cD, nullptr, q, cM, cD, cD);
        attn_kernel<<<cB * cH, 512, ATTN_SMEM>>>(q, kc + l * KVSTRIDE, vc + l * KVSTRIDE,
                                                 a, query, 0);
        split_arr(a, ahi, alo, KVSTRIDE);
        bgemm<false, true, false>(ahi, alo, whi + 7 * WBLK + l * WD, wlo + 7 * WBLK + l * WD,
                                  nullptr, x, x, cM, cD, cD);

        // --- feed forward ---
        ln_kernel<true><<<cM, 256>>>(x, ln3_g + l * cD, ln3_b + l * cD, nullptr, ahi, alo);
        bgemm<true, false, true>(ahi, alo, whi + W1OFF + l * WF1, wlo + W1OFF + l * WF1,
                                 bf1 + l * cFF, nullptr, f, cM, cFF, cD);
        split_arr(f, ahi, alo, (size_t)cM * cFF);
        bgemm<true, true, false>(ahi, alo, whi + W2OFF + l * WF1, wlo + W2OFF + l * WF1,
                                 bf2 + l * cD, x, x, cM, cD, cFF);
    }

    // final layernorm -> output
    ln_kernel<false><<<cM, 256>>>(x, lnf_g, lnf_b, (float*)d_out, nullptr, nullptr);
}

// round 16
// speedup vs baseline: 1.1121x; 1.1121x over previous
#include <cuda_runtime.h>
#include <cuda_bf16.h>
#include <math.h>
#include <stdint.h>

// ---------------- problem constants ----------------
constexpr int cB   = 32;
constexpr int cSQ  = 200;
constexpr int cSKV = 200;
constexpr int cD   = 1024;
constexpr int cH   = 16;
constexpr int cHD  = 64;
constexpr int cL   = 6;
constexpr int cFF  = 2048;
constexpr int cM   = cB * cSQ;   // 6400

// ---------------- scratch ----------------
__device__ float g_x[cM * cD];
__device__ float g_q[cM * cD];
__device__ float g_k[cM * cD];
__device__ float g_v[cM * cD];
__device__ float g_a[cM * cD];
__device__ float g_f[cM * cFF];
__device__ float g_kc[cL][cM * cD];   // precomputed cross-attn K per layer
__device__ float g_vc[cL][cM * cD];   // precomputed cross-attn V per layer

constexpr size_t WBLK  = (size_t)cL * cD * cD;
constexpr size_t W1OFF = 8 * WBLK;
constexpr size_t W1SZ  = (size_t)cL * cD * cFF;
constexpr size_t W2OFF = W1OFF + W1SZ;
constexpr size_t WTOT  = W2OFF + W1SZ;

__device__ __align__(16) __nv_bfloat16 g_whi[WTOT];
__device__ __align__(16) __nv_bfloat16 g_wlo[WTOT];
__device__ __align__(16) __nv_bfloat16 g_ahi[cM * cFF];
__device__ __align__(16) __nv_bfloat16 g_alo[cM * cFF];
__device__ __align__(16) __nv_bfloat16 g_keyhi[cM * cD];
__device__ __align__(16) __nv_bfloat16 g_keylo[cM * cD];
__device__ __align__(16) __nv_bfloat16 g_valhi[cM * cD];
__device__ __align__(16) __nv_bfloat16 g_vallo[cM * cD];

// ---------------- fp32 -> bf16 hi/lo split ----------------
__global__ void split4_kernel(const float* __restrict__ in,
                              __nv_bfloat16* __restrict__ hi,
                              __nv_bfloat16* __restrict__ lo, int n4)
{
    int i = blockIdx.x * blockDim.x + threadIdx.x;
    if (i >= n4) return;
    float4 v = reinterpret_cast<const float4*>(in)[i];
    __nv_bfloat16 h0 = __float2bfloat16(v.x);
    __nv_bfloat16 h1 = __float2bfloat16(v.y);
    __nv_bfloat16 h2 = __float2bfloat16(v.z);
    __nv_bfloat16 h3 = __float2bfloat16(v.w);
    __nv_bfloat16 l0 = __float2bfloat16(v.x - __bfloat162float(h0));
    __nv_bfloat16 l1 = __float2bfloat16(v.y - __bfloat162float(h1));
    __nv_bfloat16 l2 = __float2bfloat16(v.z - __bfloat162float(h2));
    __nv_bfloat16 l3 = __float2bfloat16(v.w - __bfloat162float(h3));
    __nv_bfloat162* H = reinterpret_cast<__nv_bfloat162*>(hi);
    __nv_bfloat162* L = reinterpret_cast<__nv_bfloat162*>(lo);
    H[2 * i]     = __nv_bfloat162(h0, h1);
    H[2 * i + 1] = __nv_bfloat162(h2, h3);
    L[2 * i]     = __nv_bfloat162(l0, l1);
    L[2 * i + 1] = __nv_bfloat162(l2, l3);
}

// ---------------- embedding + positional encoding ----------------
__global__ void embed_kernel(const int* __restrict__ tok,
                             const float* __restrict__ emb,
                             float* __restrict__ x)
{
    int idx = blockIdx.x * blockDim.x + threadIdx.x;
    if (idx >= cM * (cD / 2)) return;
    int p = idx & (cD / 2 - 1);
    int t = idx >> 9;
    int s = t % cSQ;
    int id = tok[t];
    int j = p * 2;
    float div = __powf(10000.0f, (float)j / (float)cD);
    float ang = (float)s / div;
    float sv, cv;
    sincosf(ang, &sv, &cv);
    const float* er = emb + (size_t)id * cD + j;
    float2 out;
    out.x = er[0] + sv;
    out.y = er[1] + cv;
    *reinterpret_cast<float2*>(x + (size_t)t * cD + j) = out;
}

// ---------------- layernorm (optionally writing vectorized bf16 hi/lo split) ----------------
template<bool SPLIT>
__global__ void ln_kernel(const float* __restrict__ x,
                          const float* __restrict__ g,
                          const float* __restrict__ b,
                          float* __restrict__ y,
                          __nv_bfloat16* __restrict__ hi,
                          __nv_bfloat16* __restrict__ lo)
{
    __shared__ float red[64];
    int row = blockIdx.x;
    const float* xr = x + (size_t)row * cD;
    float s = 0.f, s2 = 0.f;
    for (int i = threadIdx.x; i < cD; i += blockDim.x) {
        float v = xr[i];
        s += v;
        s2 = fmaf(v, v, s2);
    }
    #pragma unroll
    for (int o = 16; o; o >>= 1) {
        s  += __shfl_xor_sync(0xffffffffu, s,  o);
        s2 += __shfl_xor_sync(0xffffffffu, s2, o);
    }
    int w = threadIdx.x >> 5;
    if ((threadIdx.x & 31) == 0) { red[w] = s; red[32 + w] = s2; }
    __syncthreads();
    if (threadIdx.x < 32) {
        int nw = blockDim.x >> 5;
        s  = (threadIdx.x < nw) ? red[threadIdx.x]      : 0.f;
        s2 = (threadIdx.x < nw) ? red[32 + threadIdx.x] : 0.f;
        #pragma unroll
        for (int o = 16; o; o >>= 1) {
            s  += __shfl_xor_sync(0xffffffffu, s,  o);
            s2 += __shfl_xor_sync(0xffffffffu, s2, o);
        }
        if (threadIdx.x == 0) { red[0] = s; red[32] = s2; }
    }
    __syncthreads();
    float mean = red[0] * (1.0f / cD);
    float var  = red[32] * (1.0f / cD) - mean * mean;
    float inv  = rsqrtf(var + 1e-9f);
    if (SPLIT) {
        for (int i = threadIdx.x * 2; i < cD; i += blockDim.x * 2) {
            float v0 = (xr[i]     - mean) * inv * g[i]     + b[i];
            float v1 = (xr[i + 1] - mean) * inv * g[i + 1] + b[i + 1];
            __nv_bfloat16 h0 = __float2bfloat16(v0);
            __nv_bfloat16 h1 = __float2bfloat16(v1);
            __nv_bfloat16 l0 = __float2bfloat16(v0 - __bfloat162float(h0));
            __nv_bfloat16 l1 = __float2bfloat16(v1 - __bfloat162float(h1));
            *reinterpret_cast<__nv_bfloat162*>(&hi[(size_t)row * cD + i]) = __nv_bfloat162(h0, h1);
            *reinterpret_cast<__nv_bfloat162*>(&lo[(size_t)row * cD + i]) = __nv_bfloat162(l0, l1);
        }
    } else {
        float* yr = y + (size_t)row * cD;
        for (int i = threadIdx.x; i < cD; i += blockDim.x)
            yr[i] = (xr[i] - mean) * inv * g[i] + b[i];
    }
}

// ---------------- GEMM primitives ----------------
#define TBM 128
#define TBN 128
#define TBK 32

constexpr int A_ROWB = 80;
constexpr int AS_SPL = TBM * A_ROWB;         // 10240
constexpr int A_BUFB = 2 * AS_SPL;
constexpr int B_ROWB = 272;
constexpr int BS_SPL = TBK * B_ROWB;         // 8704
constexpr int B_BUFB = 2 * BS_SPL;
constexpr int STAGEB = A_BUFB + B_BUFB;      // 37888
constexpr int GEMM_SMEM = 2 * STAGEB;        // 75776

__device__ __forceinline__ void cp16(uint32_t dst, const void* src)
{
    asm volatile("cp.async.cg.shared.global [%0], [%1], 16;\n" :: "r"(dst), "l"(src));
}
__device__ __forceinline__ void cp_commit()
{
    asm volatile("cp.async.commit_group;\n");
}
template<int N> __device__ __forceinline__ void cp_wait()
{
    asm volatile("cp.async.wait_group %0;\n" :: "n"(N));
}
__device__ __forceinline__ void ldm_x4(uint32_t* r, uint32_t addr)
{
    asm volatile("ldmatrix.sync.aligned.m8n8.x4.shared.b16 {%0,%1,%2,%3}, [%4];\n"
                 : "=r"(r[0]), "=r"(r[1]), "=r"(r[2]), "=r"(r[3]) : "r"(addr));
}
__device__ __forceinline__ void ldm_x4t(uint32_t* r, uint32_t addr)
{
    asm volatile("ldmatrix.sync.aligned.m8n8.x4.trans.shared.b16 {%0,%1,%2,%3}, [%4];\n"
                 : "=r"(r[0]), "=r"(r[1]), "=r"(r[2]), "=r"(r[3]) : "r"(addr));
}
__device__ __forceinline__ void mma_bf16(float* c, const uint32_t* a, const uint32_t* b)
{
    asm volatile("mma.sync.aligned.m16n8k16.row.col.f32.bf16.bf16.f32 "
                 "{%0,%1,%2,%3}, {%4,%5,%6,%7}, {%8,%9}, {%0,%1,%2,%3};\n"
                 : "+f"(c[0]), "+f"(c[1]), "+f"(c[2]), "+f"(c[3])
                 : "r"(a[0]), "r"(a[1]), "r"(a[2]), "r"(a[3]), "r"(b[0]), "r"(b[1]));
}

template<bool HAS_BIAS, bool HAS_RES, bool DO_RELU>
__device__ __forceinline__ void gemm_body(
    int M, int N, int K,
    const __nv_bfloat16* __restrict__ Ahi,
    const __nv_bfloat16* __restrict__ Alo,
    const __nv_bfloat16* __restrict__ Bhi,
    const __nv_bfloat16* __restrict__ Blo,
    const float* __restrict__ bias,
    const float* __restrict__ R,
    float* __restrict__ C,
    char* smem)
{
    const uint32_t sb = (uint32_t)__cvta_generic_to_shared(smem);

    const int tid  = threadIdx.x;
    const int blockM = blockIdx.y * TBM;
    const int blockN = blockIdx.x * TBN;

    const int am = tid >> 1;
    const int ac = (tid & 1) * 2;
    const int bk = tid >> 3;
    const int bc = (tid & 7) * 2;

    const __nv_bfloat16* Ah = Ahi + (size_t)(blockM + am) * K;
    const __nv_bfloat16* Al = Alo + (size_t)(blockM + am) * K;

    auto load_stage = [&](int kt, int buf) {
        const uint32_t abase = sb + buf * STAGEB;
        const uint32_t bbase = sb + buf * STAGEB + A_BUFB;
        int kofs = kt * TBK;
        #pragma unroll
        for (int c = 0; c < 2; c++) {
            uint32_t d = abase + am * A_ROWB + (ac + c) * 16;
            cp16(d,           Ah + kofs + (ac + c) * 8);
            cp16(d + AS_SPL,  Al + kofs + (ac + c) * 8);
        }
        const __nv_bfloat16* Bh = Bhi + (size_t)(kofs + bk) * N + blockN;
        const __nv_bfloat16* Bl = Blo + (size_t)(kofs + bk) * N + blockN;
        #pragma unroll
        for (int c = 0; c < 2; c++) {
            uint32_t d = bbase + bk * B_ROWB + (bc + c) * 16;
            cp16(d,           Bh + (bc + c) * 8);
            cp16(d + BS_SPL,  Bl + (bc + c) * 8);
        }
    };

    const int warp = tid >> 5;
    const int lane = tid & 31;
    const int warp_m = (warp >> 2) * 64;
    const int warp_n = (warp & 3) * 32;

    const int a_row = lane & 15;
    const int a_kc  = lane >> 4;
    const int b_row = (lane & 7) + ((lane >> 3) & 1) * 8;
    const int b_nc  = (lane >> 4) * 8;

    float acc[4][4][4] = {};

    const int tiles = K / TBK;
    load_stage(0, 0);
    cp_commit();

    for (int kt = 0; kt < tiles; kt++) {
        if (kt + 1 < tiles) load_stage(kt + 1, (kt + 1) & 1);
        cp_commit();
        cp_wait<1>();
        __syncthreads();

        const int buf = kt & 1;
        const uint32_t abase = sb + buf * STAGEB;
        const uint32_t bbase = sb + buf * STAGEB + A_BUFB;

        #pragma unroll
        for (int ks = 0; ks < 2; ks++) {
            const int k0 = ks * 16;
            uint32_t ah[4][4], al[4][4];
            #pragma unroll
            for (int mt = 0; mt < 4; mt++) {
                uint32_t ar = abase + (warp_m + mt * 16 + a_row) * A_ROWB
                            + ((k0 >> 3) + a_kc) * 16;
                ldm_x4(ah[mt], ar);
                ldm_x4(al[mt], ar + AS_SPL);
            }
            uint32_t bh[4][2], bl[4][2];
            #pragma unroll
            for (int g = 0; g < 2; g++) {
                uint32_t br = bbase + (k0 + b_row) * B_ROWB
                            + (warp_n + g * 16 + b_nc) * 2;
                uint32_t r[4];
                ldm_x4t(r, br);
                bh[2 * g][0] = r[0]; bh[2 * g][1] = r[1];
                bh[2 * g + 1][0] = r[2]; bh[2 * g + 1][1] = r[3];
                ldm_x4t(r, br + BS_SPL);
                bl[2 * g][0] = r[0]; bl[2 * g][1] = r[1];
                bl[2 * g + 1][0] = r[2]; bl[2 * g + 1][1] = r[3];
            }
            #pragma unroll
            for (int mt = 0; mt < 4; mt++)
                #pragma unroll
                for (int nt = 0; nt < 4; nt++) {
                    mma_bf16(acc[mt][nt], ah[mt], bh[nt]);
                    mma_bf16(acc[mt][nt], ah[mt], bl[nt]);
                    mma_bf16(acc[mt][nt], al[mt], bh[nt]);
                }
        }
        __syncthreads();
    }

    #pragma unroll
    for (int mt = 0; mt < 4; mt++) {
        #pragma unroll
        for (int nt = 0; nt < 4; nt++) {
            int row0 = blockM + warp_m + mt * 16 + (lane >> 2);
            int col  = blockN + warp_n + nt * 8 + (lane & 3) * 2;
            #pragma unroll
            for (int h = 0; h < 2; h++) {
                int row = row0 + h * 8;
                float2 v;
                v.x = acc[mt][nt][2 * h];
                v.y = acc[mt][nt][2 * h + 1];
                if (HAS_BIAS) {
                    float2 bz = *reinterpret_cast<const float2*>(&bias[col]);
                    v.x += bz.x; v.y += bz.y;
                }
                if (HAS_RES) {
                    float2 rz = *reinterpret_cast<const float2*>(&R[(size_t)row * N + col]);
                    v.x += rz.x; v.y += rz.y;
                }
                if (DO_RELU) { v.x = fmaxf(v.x, 0.f); v.y = fmaxf(v.y, 0.f); }
                *reinterpret_cast<float2*>(&C[(size_t)row * N + col]) = v;
            }
        }
    }
}

template<bool HAS_BIAS, bool HAS_RES, bool DO_RELU>
__global__ __launch_bounds__(256, 2)
void bgemm_kernel(int M, int N, int K,
                  const __nv_bfloat16* __restrict__ Ahi,
                  const __nv_bfloat16* __restrict__ Alo,
                  const __nv_bfloat16* __restrict__ Bhi,
                  const __nv_bfloat16* __restrict__ Blo,
                  const float* __restrict__ bias,
                  const float* __restrict__ R,
                  float* __restrict__ C)
{
    extern __shared__ char smem[];
    gemm_body<HAS_BIAS, HAS_RES, DO_RELU>(M, N, K, Ahi, Alo, Bhi, Blo, bias, R, C, smem);
}

// ---- z-batched GEMM ----
struct GJob {
    const __nv_bfloat16 *Ahi, *Alo, *Bhi, *Blo;
    const float* bias;
    float* C;
};
struct GJobs { GJob j[12]; };

__global__ __launch_bounds__(256, 2)
void bgemm_batch_kernel(int M, int N, int K, GJobs jobs)
{
    extern __shared__ char smem[];
    const GJob jb = jobs.j[blockIdx.z];
    gemm_body<true, false, false>(M, N, K, jb.Ahi, jb.Alo, jb.Bhi, jb.Blo,
                                  jb.bias, nullptr, jb.C, smem);
}

// ---------------- fused attention (R14 proven version) ----------------
constexpr int ATTN_SMEM = 2 * cSKV * cHD * (int)sizeof(float);  // 102400 B

__global__ __launch_bounds__(256, 1)
void attn_kernel(const float* __restrict__ Q,
                 const float* __restrict__ Km,
                 const float* __restrict__ Vm,
                 float* __restrict__ O,
                 const int* __restrict__ tok,
                 int causal)
{
    extern __shared__ float sm[];
    float* Ks = sm;
    float* Vs = sm + cSKV * cHD;
    __shared__ int padk[cSKV];

    int bh = blockIdx.x;
    int b  = bh / cH, h = bh % cH;
    const float* Kbase = Km + (size_t)b * cSKV * cD + h * cHD;
    const float* Vbase = Vm + (size_t)b * cSKV * cD + h * cHD;

    for (int idx = threadIdx.x; idx < cSKV * cHD; idx += blockDim.x) {
        int kk = idx >> 6, d = idx & 63;
        Ks[idx] = Kbase[(size_t)kk * cD + d];
        Vs[idx] = Vbase[(size_t)kk * cD + d];
    }
    if (causal)
        for (int idx = threadIdx.x; idx < cSKV; idx += blockDim.x)
            padk[idx] = (tok[b * cSQ + idx] == 0);
    __syncthreads();

    int t = threadIdx.x;
    if (t >= cSQ) return;

    float rq[cHD];
    const float* Qr = Q + (size_t)(b * cSQ + t) * cD + h * cHD;
    #pragma unroll
    for (int d = 0; d < cHD; d++) rq[d] = Qr[d] * 0.125f;

    float m = -INFINITY, l = 0.f;
    float acc[cHD];
    #pragma unroll
    for (int d = 0; d < cHD; d++) acc[d] = 0.f;

    int kmax = causal ? (t + 1) : cSKV;
    for (int k = 0; k < kmax; k++) {
        if (causal && padk[k]) continue;
        const float* kr = &Ks[k * cHD];
        float s0 = 0.f, s1 = 0.f, s2 = 0.f, s3 = 0.f;
        #pragma unroll
        for (int d = 0; d < cHD; d += 4) {
            s0 = fmaf(rq[d + 0], kr[d + 0], s0);
            s1 = fmaf(rq[d + 1], kr[d + 1], s1);
            s2 = fmaf(rq[d + 2], kr[d + 2], s2);
            s3 = fmaf(rq[d + 3], kr[d + 3], s3);
        }
        float s  = (s0 + s1) + (s2 + s3);
        float mn = fmaxf(m, s);
        float f  = __expf(m - mn);
        float e  = __expf(s - mn);
        l = l * f + e;
        const float* vr = &Vs[k * cHD];
        #pragma unroll
        for (int d = 0; d < cHD; d++)
            acc[d] = fmaf(acc[d], f, e * vr[d]);
        m = mn;
    }
    float inv = 1.0f / l;
    float* Or = O + (size_t)(b * cSQ + t) * cD + h * cHD;
    #pragma unroll
    for (int d = 0; d < cHD; d++) Or[d] = acc[d] * inv;
}

// ---------------- host-side helpers ----------------
typedef const __nv_bfloat16* bfp;

static inline void split_arr(const float* in, __nv_bfloat16* hi, __nv_bfloat16* lo, size_t n)
{
    int n4 = (int)(n / 4);
    split4_kernel<<<(n4 + 255) / 256, 256>>>(in, hi, lo, n4);
}

template<bool HB, bool HR, bool RL>
static inline void bgemm(bfp Ahi, bfp Alo, bfp Bhi, bfp Blo,
                         const float* bias, const float* R, float* C,
                         int M, int N, int K)
{
    dim3 grid(N / TBN, M / TBM);
    bgemm_kernel<HB, HR, RL><<<grid, 256, GEMM_SMEM>>>(M, N, K, Ahi, Alo, Bhi, Blo, bias, R, C);
}

extern "C" void kernel_launch(void* const* d_in, const int* in_sizes, int n_in,
                              void* d_out, int out_size)
{
    const int*   query = (const int*)d_in[0];
    const float* key   = (const float*)d_in[1];
    const float* value = (const float*)d_in[2];
    const float* emb   = (const float*)d_in[3];

    const float* P[32];
    for (int i = 0; i < n_in && i < 32; i++) P[i] = (const float*)d_in[i];

    const float *ln1_g, *ln1_b, *ln2_g, *ln2_b, *ln3_g, *ln3_b;
    const float *Wq_s, *Wk_s, *Wv_s, *Wo_s, *Wq_c, *Wk_c, *Wv_c, *Wo_c;
    const float *bq_s, *bk_s, *bv_s, *bq_c, *bk_c, *bv_c;
    const float *W1, *bf1, *W2, *bf2, *lnf_g, *lnf_b;

    bool dict_order = (n_in > 11) && (in_sizes[11] > 1000000);
    if (dict_order) {
        ln1_g = P[4];  ln2_g = P[5];  ln3_g = P[6];
        ln1_b = P[7];  ln2_b = P[8];  ln3_b = P[9];
        Wq_s = P[10]; Wk_s = P[11]; Wv_s = P[12]; Wo_s = P[13];
        Wq_c = P[14]; Wk_c = P[15]; Wv_c = P[16]; Wo_c = P[17];
        bq_s = P[18]; bk_s = P[19]; bv_s = P[20];
        bq_c = P[21]; bk_c = P[22]; bv_c = P[23];
        W1 = P[24]; bf1 = P[25]; W2 = P[26]; bf2 = P[27];
        lnf_g = P[28]; lnf_b = P[29];
    } else {
        ln1_g = P[4];  ln1_b = P[5];  ln2_g = P[6];
        ln2_b = P[7];  ln3_g = P[8];  ln3_b = P[9];
        Wq_s = P[10]; bq_s = P[11]; Wk_s = P[12]; bk_s = P[13];
        Wv_s = P[14]; bv_s = P[15]; Wo_s = P[16];
        Wq_c = P[17]; bq_c = P[18]; Wk_c = P[19]; bk_c = P[20];
        Wv_c = P[21]; bv_c = P[22]; Wo_c = P[23];
        W1 = P[24]; bf1 = P[25]; W2 = P[26]; bf2 = P[27];
        lnf_g = P[28]; lnf_b = P[29];
    }

    float *x, *q, *k, *v, *a, *f, *kc, *vc;
    cudaGetSymbolAddress((void**)&x, g_x);
    cudaGetSymbolAddress((void**)&q, g_q);
    cudaGetSymbolAddress((void**)&k, g_k);
    cudaGetSymbolAddress((void**)&v, g_v);
    cudaGetSymbolAddress((void**)&a, g_a);
    cudaGetSymbolAddress((void**)&f, g_f);
    cudaGetSymbolAddress((void**)&kc, g_kc);
    cudaGetSymbolAddress((void**)&vc, g_vc);

    __nv_bfloat16 *whi, *wlo, *ahi, *alo, *khi, *klo, *vhi, *vlo;
    cudaGetSymbolAddress((void**)&whi, g_whi);
    cudaGetSymbolAddress((void**)&wlo, g_wlo);
    cudaGetSymbolAddress((void**)&ahi, g_ahi);
    cudaGetSymbolAddress((void**)&alo, g_alo);
    cudaGetSymbolAddress((void**)&khi, g_keyhi);
    cudaGetSymbolAddress((void**)&klo, g_keylo);
    cudaGetSymbolAddress((void**)&vhi, g_valhi);
    cudaGetSymbolAddress((void**)&vlo, g_vallo);

    cudaFuncSetAttribute(attn_kernel,
                         cudaFuncAttributeMaxDynamicSharedMemorySize, ATTN_SMEM);
    cudaFuncSetAttribute(bgemm_kernel<true, false, false>,
                         cudaFuncAttributeMaxDynamicSharedMemorySize, GEMM_SMEM);
    cudaFuncSetAttribute(bgemm_kernel<true, false, true>,
                         cudaFuncAttributeMaxDynamicSharedMemorySize, GEMM_SMEM);
    cudaFuncSetAttribute(bgemm_kernel<false, true, false>,
                         cudaFuncAttributeMaxDynamicSharedMemorySize, GEMM_SMEM);
    cudaFuncSetAttribute(bgemm_kernel<true, true, false>,
                         cudaFuncAttributeMaxDynamicSharedMemorySize, GEMM_SMEM);
    cudaFuncSetAttribute(bgemm_batch_kernel,
                         cudaFuncAttributeMaxDynamicSharedMemorySize, GEMM_SMEM);

    const size_t WD  = (size_t)cD * cD;
    const size_t WF1 = (size_t)cD * cFF;
    const size_t KVSTRIDE = (size_t)cM * cD;

    // ---- launches 1-5: splits needed by the cross-KV batch ----
    split_arr(key,   khi, klo, KVSTRIDE);                          // 1
    split_arr(value, vhi, vlo, KVSTRIDE);                          // 2
    split_arr(Wk_c, whi + 5 * WBLK, wlo + 5 * WBLK, WBLK);         // 3
    split_arr(Wv_c, whi + 6 * WBLK, wlo + 6 * WBLK, WBLK);         // 4
    split_arr(Wq_s, whi + 0 * WBLK, wlo + 0 * WBLK, WBLK);         // 5

    // ---- launch 6 (profiled): all 12 cross-attn K/V GEMMs in one batch ----
    {
        GJobs jobs;
        for (int l = 0; l < cL; l++) {
            jobs.j[2 * l]     = { khi, klo, whi + 5 * WBLK + l * WD, wlo + 5 * WBLK + l * WD,
                                  bk_c + l * cD, kc + l * KVSTRIDE };
            jobs.j[2 * l + 1] = { vhi, vlo, whi + 6 * WBLK + l * WD, wlo + 6 * WBLK + l * WD,
                                  bv_c + l * cD, vc + l * KVSTRIDE };
        }
        dim3 grid(cD / TBN, cM / TBM, 12);
        bgemm_batch_kernel<<<grid, 256, GEMM_SMEM>>>(cM, cD, cD, jobs);
    }

    // ---- remaining weight splits ----
    split_arr(Wk_s, whi + 1 * WBLK, wlo + 1 * WBLK, WBLK);
    split_arr(Wv_s, whi + 2 * WBLK, wlo + 2 * WBLK, WBLK);
    split_arr(Wo_s, whi + 3 * WBLK, wlo + 3 * WBLK, WBLK);
    split_arr(Wq_c, whi + 4 * WBLK, wlo + 4 * WBLK, WBLK);
    split_arr(Wo_c, whi + 7 * WBLK, wlo + 7 * WBLK, WBLK);
    split_arr(W1, whi + W1OFF, wlo + W1OFF, W1SZ);
    split_arr(W2, whi + W2OFF, wlo + W2OFF, W1SZ);

    // x = emb[query] + PE
    embed_kernel<<<(cM * (cD / 2) + 255) / 256, 256>>>(query, emb, x);

    for (int l = 0; l < cL; l++) {
        // --- self attention: LN(fused split) -> batched QKV -> attn -> Wo(+res) ---
        ln_kernel<true><<<cM, 256>>>(x, ln1_g + l * cD, ln1_b + l * cD, nullptr, ahi, alo);
        {
            GJobs jobs;
            jobs.j[0] = { ahi, alo, whi + 0 * WBLK + l * WD, wlo + 0 * WBLK + l * WD,
                          bq_s + l * cD, q };
            jobs.j[1] = { ahi, alo, whi + 1 * WBLK + l * WD, wlo + 1 * WBLK + l * WD,
                          bk_s + l * cD, k };
            jobs.j[2] = { ahi, alo, whi + 2 * WBLK + l * WD, wlo + 2 * WBLK + l * WD,
                          bv_s + l * cD, v };
            dim3 grid(cD / TBN, cM / TBM, 3);
            bgemm_batch_kernel<<<grid, 256, GEMM_SMEM>>>(cM, cD, cD, jobs);
        }
        attn_kernel<<<cB * cH, 256, ATTN_SMEM>>>(q, k, v, a, query, 1);
        split_arr(a, ahi, alo, KVSTRIDE);
        bgemm<false, true, false>(ahi, alo, whi + 3 * WBLK + l * WD, wlo + 3 * WBLK + l * WD,
                                  nullptr, x, x, cM, cD, cD);

        // --- cross attention (K,V precomputed) ---
        ln_kernel<true><<<cM, 256>>>(x, ln2_g + l * cD, ln2_b + l * cD, nullptr, ahi, alo);
        bgemm<true, false, false>(ahi, alo, whi + 4 * WBLK + l * WD, wlo + 4 * WBLK + l * WD,
                                  bq_c + l * cD, nullptr, q, cM, cD, cD);
        attn_kernel<<<cB * cH, 256, ATTN_SMEM>>>(q, kc + l * KVSTRIDE, vc + l * KVSTRIDE,
                                                 a, query, 0);
        split_arr(a, ahi, alo, KVSTRIDE);
        bgemm<false, true, false>(ahi, alo, whi + 7 * WBLK + l * WD, wlo + 7 * WBLK + l * WD,
                                  nullptr, x, x, cM, cD, cD);

        // --- feed forward ---
        ln_kernel<true><<<cM, 256>>>(x, ln3_g + l * cD, ln3_b + l * cD, nullptr, ahi, alo);
        bgemm<true, false, true>(ahi, alo, whi + W1OFF + l * WF1, wlo + W1OFF + l * WF1,
                                 bf1 + l * cFF, nullptr, f, cM, cFF, cD);
        split_arr(f, ahi, alo, (size_t)cM * cFF);
        bgemm<true, true, false>(ahi, alo, whi + W2OFF + l * WF1, wlo + W2OFF + l * WF1,
                                 bf2 + l * cD, x, x, cM, cD, cFF);
    }

    // final layernorm -> output
    ln_kernel<false><<<cM, 256>>>(x, lnf_g, lnf_b, (float*)d_out, nullptr, nullptr);
}